// round 10
// baseline (speedup 1.0000x reference)
#include <cuda_runtime.h>
#include <math.h>
#include <stdint.h>

typedef unsigned long long u64;

#define DD 256
#define BB 8
#define CHK 64
#define NC 64
#define TLEN 4096
#define SA 260
#define STB 34
#define XTILE (16*SA)
#define PB1 (256*STB)

static __device__ float S_w1f [4][BB][DD*DD];
static __device__ float S_w1fT[4][BB][DD*DD];
static __device__ float S_w2  [6][BB][DD*DD];
static __device__ float S_w1v [2][BB][DD];
static __device__ float S_wsk [2][BB][DD];

static __device__ float SC_k [BB][CHK*DD];
static __device__ float SC_v [BB][CHK*DD];
static __device__ float SC_q [BB][CHK*DD];
static __device__ float SC_h2[6][BB][CHK*DD];
static __device__ float SC_g [4][BB][CHK*DD];
static __device__ float SC_pre[6][BB][CHK*DD];
static __device__ float SC_eta[BB][CHK];
static __device__ float SC_alpha[BB][CHK];
static __device__ float SC_vsum[BB][CHK];
static __device__ float SC_gs[2][BB][CHK];
static __device__ float SC_abar[BB];

__device__ __forceinline__ void fmaX2(u64 &d, u64 a, u64 b){
    asm("fma.rn.f32x2 %0, %1, %2, %0;" : "+l"(d) : "l"(a), "l"(b));
}
__device__ __forceinline__ u64 pk2(float lo, float hi){
    u64 r; asm("mov.b64 %0, {%1, %2};" : "=l"(r) : "f"(lo), "f"(hi)); return r;
}
__device__ __forceinline__ float2 up2(u64 v){
    float lo, hi; asm("mov.b64 {%0, %1}, %2;" : "=f"(lo), "=f"(hi) : "l"(v));
    return make_float2(lo, hi);
}
__device__ __forceinline__ float red2(u64 v){ float2 t = up2(v); return t.x + t.y; }
__device__ __forceinline__ float geluf(float z){
    return 0.5f*z*(1.0f + erff(z*0.70710678118654752f));
}
__device__ __forceinline__ float dgeluf(float z){
    float cdf = 0.5f*(1.0f + erff(z*0.70710678118654752f));
    float pdf = expf(-0.5f*z*z)*0.39894228040143267f;
    return cdf + z*pdf;
}
__device__ __forceinline__ float warp_sum(float v){
    #pragma unroll
    for(int o=16;o>0;o>>=1) v += __shfl_xor_sync(0xffffffffu, v, o);
    return v;
}
__device__ __forceinline__ void load_tile16(float* dst, const float* __restrict__ src){
    const int tid = threadIdx.x;
    #pragma unroll
    for(int l=0;l<4;l++){
        int idx = tid + l*256;
        int r = idx>>6, qc = (idx&63)<<2;
        *reinterpret_cast<float4*>(dst + r*SA + qc) =
            *reinterpret_cast<const float4*>(src + r*DD + qc);
    }
}

// TB GEMM, 256 thr: OUT[t,col]=sum_c A[t,c]*B[col,c].
// rw=wid&1 -> rows rw*8..+7 ; jh=wid>>1 -> cols jh*64+tx+32*jj (jj<2). acc packed (even,odd) k.
__device__ __forceinline__ void gemmTB(const float* As, const float* __restrict__ Bg,
                                       float* Bt, u64 (&acc)[8][2]){
    const int tid = threadIdx.x, tx = tid&31;
    const int rw = (tid>>5)&1, jh = tid>>6;
    #pragma unroll
    for(int r=0;r<8;r++){ acc[r][0]=0ull; acc[r][1]=0ull; }
    const uint32_t a_base = (uint32_t)__cvta_generic_to_shared(As) + (uint32_t)(rw*8*SA*4);

    for(int p=0;p<8;p++){
        #pragma unroll
        for(int l=0;l<8;l++){
            int idx = tid + l*256;
            int j = idx>>3, qc = (idx&7)<<2;
            float4 v = *reinterpret_cast<const float4*>(Bg + (size_t)j*DD + p*32 + qc);
            float2* w = reinterpret_cast<float2*>(Bt + j*STB + qc);
            w[0] = make_float2(v.x, v.y);
            w[1] = make_float2(v.z, v.w);
        }
        __syncthreads();
        const float* Bl = Bt + (jh*64 + tx)*STB;
        const uint32_t a_p = a_base + (uint32_t)(p*128);
        #pragma unroll
        for(int q=0;q<8;q++){
            u64 al[8], ah[8];
            #pragma unroll
            for(int r=0;r<8;r++)
                asm("ld.shared.v2.u64 {%0,%1}, [%2];"
                    : "=l"(al[r]), "=l"(ah[r]) : "r"(a_p + (uint32_t)(r*SA*4 + q*16)));
            #pragma unroll
            for(int jj=0;jj<2;jj++){
                u64 b0 = *reinterpret_cast<const u64*>(Bl + jj*32*STB + q*4);
                u64 b1 = *reinterpret_cast<const u64*>(Bl + jj*32*STB + q*4 + 2);
                #pragma unroll
                for(int r=0;r<8;r++) fmaX2(acc[r][jj], al[r], b0);
                #pragma unroll
                for(int r=0;r<8;r++) fmaX2(acc[r][jj], ah[r], b1);
            }
        }
        __syncthreads();
    }
}

__global__ void k0_init(const float* __restrict__ k1w, const float* __restrict__ k2w,
                        const float* __restrict__ v1w, const float* __restrict__ v2w,
                        const float* __restrict__ q1w, const float* __restrict__ q2w,
                        const float* __restrict__ e1w, const float* __restrict__ e2w,
                        const float* __restrict__ esw, const float* __restrict__ a1w,
                        const float* __restrict__ a2w, const float* __restrict__ asw,
                        const float* __restrict__ m1w, const float* __restrict__ m2w){
    const int gid = blockIdx.x*blockDim.x + threadIdx.x;
    const int m = blockIdx.y;
    if(m<4){
        const float* src = (m==0)?k1w:(m==1)?v1w:(m==2)?q1w:m1w;
        float v = src[gid];
        #pragma unroll
        for(int b=0;b<BB;b++) S_w1f[m][b][gid] = v;
    } else if(m<10){
        const int s = m-4;
        const float* src = (s==0)?k2w:(s==1)?v2w:(s==2)?q2w:(s==3)?e2w:(s==4)?a2w:m2w;
        float v = src[gid];
        #pragma unroll
        for(int b=0;b<BB;b++) S_w2[s][b][gid] = v;
    } else if(m<14){
        const int f = m-10;
        const float* src = (f==0)?k1w:(f==1)?v1w:(f==2)?q1w:m1w;
        float v = src[(gid&255)*DD + (gid>>8)];
        #pragma unroll
        for(int b=0;b<BB;b++) S_w1fT[f][b][gid] = v;
    } else if(gid < DD){
        #pragma unroll
        for(int b=0;b<BB;b++){
            S_w1v[0][b][gid] = e1w[gid];
            S_w1v[1][b][gid] = a1w[gid];
            S_wsk[0][b][gid] = esw[gid];
            S_wsk[1][b][gid] = asw[gid];
        }
    }
}

__global__ void __launch_bounds__(256,2) k1_forward(const float* __restrict__ x, int chunk){
    extern __shared__ float sm[];
    float* Xs  = sm;
    float* Hs  = sm + XTILE;
    float* Bt  = sm + 2*XTILE;
    float* Red = sm + 2*XTILE + PB1;
    const int tid = threadIdx.x, tx = tid&31;
    const int rw = (tid>>5)&1, jh = tid>>6;
    const int bx = blockIdx.x;
    const int th = bx&3, gg = (bx>>2)&3, b = bx>>4;
    const int tok0 = chunk*CHK + th*16;

    load_tile16(Xs, x + ((size_t)b*TLEN + tok0)*DD);

    u64 acc[8][2];
    if(gg < 3){
        gemmTB(Xs, S_w2[gg][b], Bt, acc);
        #pragma unroll
        for(int r=0;r<8;r++)
            #pragma unroll
            for(int jj=0;jj<2;jj++)
                Hs[(rw*8+r)*SA + jh*64 + tx + 32*jj] = geluf(red2(acc[r][jj]));
        gemmTB(Hs, S_w1f[gg][b], Bt, acc);

        float out[8][2];
        #pragma unroll
        for(int r=0;r<8;r++){
            const int r2 = rw*8+r;
            float s = 0.f;
            #pragma unroll
            for(int jj=0;jj<2;jj++){
                const int col = jh*64 + tx + 32*jj;
                float o = Xs[r2*SA + col] + red2(acc[r][jj]);
                out[r][jj] = o;
                s += (gg==1)? o : o*o;
            }
            s = warp_sum(s);
            if(tx==0) Red[r2*4 + jh] = s;
        }
        __syncthreads();
        if(gg==1){
            #pragma unroll
            for(int r=0;r<8;r++){
                const int r2 = rw*8+r, row = th*16 + r2;
                #pragma unroll
                for(int jj=0;jj<2;jj++)
                    SC_v[b][row*DD + jh*64 + tx + 32*jj] = out[r][jj];
                if(jh==0 && tx==0)
                    SC_vsum[b][row] = Red[r2*4]+Red[r2*4+1]+Red[r2*4+2]+Red[r2*4+3];
            }
        } else {
            float* dst = (gg==0)? SC_k[b] : SC_q[b];
            #pragma unroll
            for(int r=0;r<8;r++){
                const int r2 = rw*8+r, row = th*16 + r2;
                float tot = Red[r2*4]+Red[r2*4+1]+Red[r2*4+2]+Red[r2*4+3];
                float inv = 1.f / fmaxf(sqrtf(tot), 1e-6f);
                #pragma unroll
                for(int jj=0;jj<2;jj++)
                    dst[row*DD + jh*64 + tx + 32*jj] = out[r][jj]*inv;
            }
        }
    } else {
        #pragma unroll 1
        for(int si=0;si<2;si++){
            gemmTB(Xs, S_w2[3+si][b], Bt, acc);
            const float* wsk = S_wsk[si][b];
            const float* w1v = S_w1v[si][b];
            #pragma unroll
            for(int r=0;r<8;r++){
                const int r2 = rw*8+r;
                float p = 0.f;
                #pragma unroll
                for(int jj=0;jj<2;jj++){
                    const int col = jh*64 + tx + 32*jj;
                    float h = geluf(red2(acc[r][jj]));
                    p += Xs[r2*SA + col]*wsk[col] + h*w1v[col];
                }
                p = warp_sum(p);
                if(tx==0) Red[r2*4 + jh] = p;
            }
            __syncthreads();
            if(jh==0 && tx==0){
                #pragma unroll
                for(int r=0;r<8;r++){
                    const int r2 = rw*8+r, row = th*16 + r2;
                    float pt = Red[r2*4]+Red[r2*4+1]+Red[r2*4+2]+Red[r2*4+3];
                    if(si==0){ float sp = (pt>20.f)? pt : log1pf(expf(pt)); SC_eta[b][row] = sp*0.001f; }
                    else       SC_alpha[b][row] = 1.f/(1.f+expf(-pt));
                }
            }
            __syncthreads();
        }
    }
}

__global__ void __launch_bounds__(256,2) k2_token(float* __restrict__ dout, int chunk){
    extern __shared__ float sm[];
    float* T0  = sm;
    float* T1  = sm + XTILE;
    float* Bt  = sm + 2*XTILE;
    float* Red = sm + 2*XTILE + PB1;
    const int tid = threadIdx.x, tx = tid&31;
    const int rw = (tid>>5)&1, jh = tid>>6;
    const int bx = blockIdx.x;
    u64 acc[8][2];

    if(bx < 128){
        const int th = bx&3, f = (bx>>2)&3, b = bx>>4;
        const int s = (f==3)? 5 : f;

        load_tile16(T0, SC_k[b] + th*16*DD);

        float zreg[8][2];
        gemmTB(T0, S_w2[s][b], Bt, acc);
        #pragma unroll
        for(int r=0;r<8;r++)
            #pragma unroll
            for(int jj=0;jj<2;jj++){
                const int r2 = rw*8+r, col = jh*64 + tx + 32*jj;
                float z = red2(acc[r][jj]); zreg[r][jj] = z;
                float h = geluf(z);
                T1[r2*SA + col] = h;
                SC_h2[s][b][(th*16 + r2)*DD + col] = h;
            }
        gemmTB(T1, S_w1f[f][b], Bt, acc);
        #pragma unroll
        for(int r=0;r<8;r++)
            #pragma unroll
            for(int jj=0;jj<2;jj++){
                const int r2 = rw*8+r, col = jh*64 + tx + 32*jj;
                const int row = th*16 + r2;
                float g = 2.f*(T0[r2*SA + col] + red2(acc[r][jj]) - SC_v[b][row*DD + col]);
                SC_g[f][b][row*DD + col] = g;
                T0[r2*SA + col] = g;
            }
        __syncthreads();
        gemmTB(T0, S_w1fT[f][b], Bt, acc);
        #pragma unroll
        for(int r=0;r<8;r++)
            #pragma unroll
            for(int jj=0;jj<2;jj++){
                const int r2 = rw*8+r, col = jh*64 + tx + 32*jj;
                SC_pre[s][b][(th*16 + r2)*DD + col] = red2(acc[r][jj])*dgeluf(zreg[r][jj]);
            }
    } else if(bx < 192){
        const int i = bx-128, th = i&3, si = (i>>2)&1, b = i>>3;
        const int s = 3+si;

        load_tile16(T0, SC_k[b] + th*16*DD);

        gemmTB(T0, S_w2[s][b], Bt, acc);
        const float* wsk = S_wsk[si][b];
        const float* w1v = S_w1v[si][b];
        float zr[8][2];
        #pragma unroll
        for(int r=0;r<8;r++){
            const int r2 = rw*8+r;
            float p = 0.f;
            #pragma unroll
            for(int jj=0;jj<2;jj++){
                const int col = jh*64 + tx + 32*jj;
                float z = red2(acc[r][jj]); zr[r][jj] = z;
                float h = geluf(z);
                SC_h2[s][b][(th*16 + r2)*DD + col] = h;
                p += T0[r2*SA + col]*wsk[col] + h*w1v[col];
            }
            p = warp_sum(p);
            if(tx==0) Red[r2*4 + jh] = p;
        }
        __syncthreads();
        #pragma unroll
        for(int r=0;r<8;r++){
            const int r2 = rw*8+r, row = th*16 + r2;
            float pt = Red[r2*4]+Red[r2*4+1]+Red[r2*4+2]+Red[r2*4+3];
            float g = 2.f*(256.f*pt - SC_vsum[b][row]);
            if(jh==0 && tx==0) SC_gs[si][b][row] = g;
            #pragma unroll
            for(int jj=0;jj<2;jj++){
                const int col = jh*64 + tx + 32*jj;
                SC_pre[s][b][row*DD + col] = g * w1v[col] * dgeluf(zr[r][jj]);
            }
        }
    } else {
        const int i = bx-192, th = i&3, b = i>>2;

        load_tile16(T0, SC_q[b] + th*16*DD);

        gemmTB(T0, S_w2[5][b], Bt, acc);
        #pragma unroll
        for(int r=0;r<8;r++)
            #pragma unroll
            for(int jj=0;jj<2;jj++)
                T1[(rw*8+r)*SA + jh*64 + tx + 32*jj] = geluf(red2(acc[r][jj]));
        gemmTB(T1, S_w1f[3][b], Bt, acc);
        #pragma unroll
        for(int r=0;r<8;r++)
            #pragma unroll
            for(int jj=0;jj<2;jj++){
                const int r2 = rw*8+r, col = jh*64 + tx + 32*jj;
                size_t off = ((size_t)b*TLEN + (size_t)chunk*CHK + th*16 + r2)*DD + col;
                dout[off] = T0[r2*SA + col] + red2(acc[r][jj]);
            }
        if(th==0 && tid==0){
            float p = 1.f;
            #pragma unroll
            for(int t=0;t<CHK;t++) p *= SC_alpha[b][t];
            SC_abar[b] = p;
        }
    }
}

__global__ void __launch_bounds__(256) k3_weights(){
    extern __shared__ float sm[];
    float* Ges = sm;
    float* Bs  = sm + 64*66;
    const int tid = threadIdx.x, wid = tid>>5, tx = tid&31;
    const int bx = blockIdx.x;

    if(bx < 640){
        int b, ot, ch;
        const float *A, *Bsrc; float* W; float* WT = 0;
        if(bx < 512){
            b = bx>>6; int r = bx&63;
            int f = r>>4, m = (r>>3)&1; ot = (r>>1)&3; ch = r&1;
            int s = (f==3)? 5 : f;
            if(m==0){ A = SC_g[f][b];   Bsrc = SC_h2[s][b]; W = S_w1f[f][b]; WT = S_w1fT[f][b]; }
            else    { A = SC_pre[s][b]; Bsrc = SC_k[b];     W = S_w2[s][b]; }
        } else {
            int i = bx-512; b = i>>4; int r = i&15;
            int si = r>>3; ot = (r>>1)&3; ch = r&1;
            A = SC_pre[3+si][b]; Bsrc = SC_k[b]; W = S_w2[3+si][b];
        }
        const float abar = SC_abar[b];
        const float* eta = SC_eta[b];

        #pragma unroll
        for(int l=0;l<8;l++){
            int idx = tid + l*256;
            int t = idx>>5, qc = (idx&31)<<2;
            *reinterpret_cast<float4*>(Bs + t*132 + qc) =
                *reinterpret_cast<const float4*>(Bsrc + t*DD + ch*128 + qc);
        }
        #pragma unroll
        for(int l=0;l<4;l++){
            int idx = tid + l*256;
            int t = idx>>4, oq = (idx&15)<<2;
            float e = eta[t];
            float4 v = *reinterpret_cast<const float4*>(A + t*DD + ot*64 + oq);
            float2* p = reinterpret_cast<float2*>(Ges + t*66 + oq);
            p[0] = make_float2(v.x*e, v.y*e);
            p[1] = make_float2(v.z*e, v.w*e);
        }
        __syncthreads();

        u64 acc[4][4];
        #pragma unroll
        for(int rp=0;rp<4;rp++)
            #pragma unroll
            for(int j=0;j<4;j++) acc[rp][j] = 0ull;

        #pragma unroll 4
        for(int t=0;t<64;t++){
            u64 a[4];
            #pragma unroll
            for(int rp=0;rp<4;rp++)
                a[rp] = *reinterpret_cast<const u64*>(Ges + t*66 + wid*8 + 2*rp);
            float4 bv = *reinterpret_cast<const float4*>(Bs + t*132 + tx*4);
            u64 b0 = pk2(bv.x,bv.x), b1 = pk2(bv.y,bv.y), b2 = pk2(bv.z,bv.z), b3 = pk2(bv.w,bv.w);
            #pragma unroll
            for(int rp=0;rp<4;rp++){
                fmaX2(acc[rp][0], a[rp], b0);
                fmaX2(acc[rp][1], a[rp], b1);
                fmaX2(acc[rp][2], a[rp], b2);
                fmaX2(acc[rp][3], a[rp], b3);
            }
        }
        #pragma unroll
        for(int rp=0;rp<4;rp++){
            const int row0 = ot*64 + wid*8 + 2*rp;
            size_t off0 = (size_t)row0*DD + ch*128 + tx*4;
            float4 w0 = *reinterpret_cast<const float4*>(W + off0);
            float4 w1 = *reinterpret_cast<const float4*>(W + off0 + DD);
            float2 c0 = up2(acc[rp][0]), c1 = up2(acc[rp][1]);
            float2 c2 = up2(acc[rp][2]), c3 = up2(acc[rp][3]);
            float4 o0 = make_float4(abar*w0.x - c0.x, abar*w0.y - c1.x,
                                    abar*w0.z - c2.x, abar*w0.w - c3.x);
            float4 o1 = make_float4(abar*w1.x - c0.y, abar*w1.y - c1.y,
                                    abar*w1.z - c2.y, abar*w1.w - c3.y);
            *reinterpret_cast<float4*>(W + off0)      = o0;
            *reinterpret_cast<float4*>(W + off0 + DD) = o1;
            if(WT){
                const int hc = ch*128 + tx*4;
                WT[(size_t)(hc+0)*DD + row0]   = o0.x;
                WT[(size_t)(hc+1)*DD + row0]   = o0.y;
                WT[(size_t)(hc+2)*DD + row0]   = o0.z;
                WT[(size_t)(hc+3)*DD + row0]   = o0.w;
                WT[(size_t)(hc+0)*DD + row0+1] = o1.x;
                WT[(size_t)(hc+1)*DD + row0+1] = o1.y;
                WT[(size_t)(hc+2)*DD + row0+1] = o1.z;
                WT[(size_t)(hc+3)*DD + row0+1] = o1.w;
            }
        }
    } else {
        const int i = bx-640, b = i>>1, si = i&1, s = 3+si;
        const float abar = SC_abar[b];
        const int j = tid;
        float aA = 0.f, aB = 0.f;
        #pragma unroll 4
        for(int t=0;t<CHK;t++){
            float ge = SC_gs[si][b][t]*SC_eta[b][t];
            aA += ge * SC_h2[s][b][t*DD + j];
            aB += ge * SC_k[b][t*DD + j];
        }
        S_w1v[si][b][j] = abar*S_w1v[si][b][j] - aA;
        S_wsk[si][b][j] = abar*S_wsk[si][b][j] - aB;
    }
}

#define SMEM12 ((2*XTILE + PB1 + 64)*4)
#define SMEM3  ((64*66 + 64*132)*4)

extern "C" void kernel_launch(void* const* d_in, const int* in_sizes, int n_in,
                              void* d_out, int out_size){
    (void)in_sizes; (void)n_in; (void)out_size;
    const float* x   = (const float*)d_in[0];
    const float* k1w = (const float*)d_in[1];
    const float* k2w = (const float*)d_in[2];
    const float* v1w = (const float*)d_in[3];
    const float* v2w = (const float*)d_in[4];
    const float* q1w = (const float*)d_in[5];
    const float* q2w = (const float*)d_in[6];
    const float* e1w = (const float*)d_in[7];
    const float* e2w = (const float*)d_in[8];
    const float* esw = (const float*)d_in[9];
    const float* a1w = (const float*)d_in[10];
    const float* a2w = (const float*)d_in[11];
    const float* asw = (const float*)d_in[12];
    const float* m1w = (const float*)d_in[13];
    const float* m2w = (const float*)d_in[14];
    float* out = (float*)d_out;

    cudaFuncSetAttribute(k1_forward, cudaFuncAttributeMaxDynamicSharedMemorySize, SMEM12);
    cudaFuncSetAttribute(k2_token,   cudaFuncAttributeMaxDynamicSharedMemorySize, SMEM12);
    cudaFuncSetAttribute(k3_weights, cudaFuncAttributeMaxDynamicSharedMemorySize, SMEM3);

    k0_init<<<dim3(DD*DD/256, 15), 256>>>(k1w,k2w,v1w,v2w,q1w,q2w,e1w,e2w,esw,a1w,a2w,asw,m1w,m2w);

    for(int c=0;c<NC;c++){
        k1_forward<<<128, 256, SMEM12>>>(x, c);
        k2_token  <<<224, 256, SMEM12>>>(out, c);
        k3_weights<<<656, 256, SMEM3>>>();
    }
}